// round 2
// baseline (speedup 1.0000x reference)
#include <cuda_runtime.h>

#define FDIM 128
#define TNODES 8
#define THREADS 256
#define GRIDSZ 444
#define MAXN 50001
#define MAXE 1000000

// Scratch (device globals: allocation-free per harness rules)
__device__ unsigned int g_or;            // 0 => edge dtype is int64, nonzero => int32
__device__ int g_row_ptr[MAXN];          // CSR row pointers over sorted-u COO
__device__ int g_v[MAXE];                // v indices converted to int32

// ---------------------------------------------------------------------------
// Detect edge dtype. For int64 edges, the odd 32-bit words of the u-row are
// all zero (u < 50000); for int32 they are v/u values and cannot all be zero.
__global__ void detect_k(const unsigned int* __restrict__ w, int E) {
    unsigned int local = 0;
    for (int i = blockIdx.x * blockDim.x + threadIdx.x; i < E;
         i += gridDim.x * blockDim.x)
        local |= w[2 * i + 1];
    if (local) atomicOr(&g_or, 1u);
}

// Convert v indices (second row of edge_index) to int32 scratch.
__global__ void convert_k(const void* __restrict__ edges, int E) {
    const bool is64 = (g_or == 0);
    const long long* e64 = (const long long*)edges;
    const int* e32 = (const int*)edges;
    for (int j = blockIdx.x * blockDim.x + threadIdx.x; j < E;
         j += gridDim.x * blockDim.x)
        g_v[j] = is64 ? (int)e64[E + j] : e32[E + j];
}

// Build CSR row_ptr by lower_bound binary search per node (u is sorted).
__global__ void rowptr_k(const void* __restrict__ edges, int E, int nN) {
    const bool is64 = (g_or == 0);
    const long long* e64 = (const long long*)edges;
    const int* e32 = (const int*)edges;
    int node = blockIdx.x * blockDim.x + threadIdx.x;
    if (node > nN) return;
    if (node == nN) { g_row_ptr[nN] = E; return; }
    int lo = 0, hi = E;
    long long key = (long long)node;
    while (lo < hi) {
        int mid = (lo + hi) >> 1;
        long long um = is64 ? e64[mid] : (long long)e32[mid];
        if (um < key) lo = mid + 1; else hi = mid;
    }
    g_row_ptr[node] = lo;
}

// ---------------------------------------------------------------------------
// Packed f32x2 helpers (Blackwell FFMA2/FADD2 — PTX only)
__device__ __forceinline__ void fma2(unsigned long long& acc,
                                     unsigned long long a,
                                     unsigned long long b) {
    asm("fma.rn.f32x2 %0, %1, %2, %0;" : "+l"(acc) : "l"(a), "l"(b));
}
__device__ __forceinline__ void add2(unsigned long long& acc,
                                     unsigned long long a) {
    asm("add.rn.f32x2 %0, %0, %1;" : "+l"(acc) : "l"(a));
}
__device__ __forceinline__ unsigned long long packf2(float lo, float hi) {
    unsigned long long r;
    asm("mov.b64 %0, {%1, %2};" : "=l"(r) : "f"(lo), "f"(hi));
    return r;
}
__device__ __forceinline__ float2 unpackf2(unsigned long long v) {
    float2 r;
    asm("mov.b64 {%0, %1}, %2;" : "=f"(r.x), "=f"(r.y) : "l"(v));
    return r;
}

// ---------------------------------------------------------------------------
// Fused kernel, k-split layout:
//   256 threads = 2 half-groups of 128. Thread (half, f) owns W[64*half ..
//   64*half+64)[f] in 32 f32x2 registers (64 regs instead of 128 -> 24
//   warps/SM instead of 12).
//   Per tile of TNODES=8 nodes:
//     gather: warp w aggregates node tile*8+w into smem (double-buffered),
//             issued immediately after the GEMM so the L2 latency overlaps
//             with other blocks' FMA phases.
//     GEMM:   each thread accumulates its k-half partial for 8 nodes x 1
//             feature via FFMA2; halves combined through a smem reduction.
__global__ void __launch_bounds__(THREADS, 3) fused_k(
    const float* __restrict__ x, const float* __restrict__ Wm,
    const float* __restrict__ bias, float* __restrict__ out, int nN) {
    __shared__ __align__(16) float agg[2][TNODES][FDIM];
    __shared__ __align__(16) float red[TNODES][FDIM];

    const int tid = threadIdx.x;
    const int warp = tid >> 5, lane = tid & 31;
    const int half = tid >> 7;
    const int f = tid & 127;

    // Preload this thread's W half-column as 32 packed f32x2 pairs (64 regs).
    unsigned long long w2[32];
#pragma unroll
    for (int j = 0; j < 32; j++)
        w2[j] = packf2(Wm[(64 * half + 2 * j) * FDIM + f],
                       Wm[(64 * half + 2 * j + 1) * FDIM + f]);
    const float b = bias[f];

    const float4* __restrict__ xr = (const float4*)x;
    const int ntiles = (nN + TNODES - 1) / TNODES;

    // ---- initial gather into buffer 0 ----
    int tile = blockIdx.x;
    if (tile < ntiles) {
        const int node = tile * TNODES + warp;
        unsigned long long a0 = 0ull, a1 = 0ull;
        if (node < nN) {
            const int s = g_row_ptr[node];
            const int e = g_row_ptr[node + 1];
#pragma unroll 4
            for (int j = s; j < e; j++) {
                const int v = g_v[j];
                const ulonglong2 xv =
                    *(const ulonglong2*)&xr[(size_t)v * (FDIM / 4) + lane];
                add2(a0, xv.x);
                add2(a1, xv.y);
            }
        }
        *(ulonglong2*)&agg[0][warp][lane * 4] = make_ulonglong2(a0, a1);
    }

    int it = 0;
    for (; tile < ntiles; tile += gridDim.x, it++) {
        __syncthreads();  // current buffer filled; previous buffer free
        const int cur = it & 1;

        // ---- GEMM on agg[cur]: partial over my k-half ----
        unsigned long long acc[TNODES];
#pragma unroll
        for (int t = 0; t < TNODES; t++) acc[t] = 0ull;
#pragma unroll
        for (int q2 = 0; q2 < 16; q2++) {
            const unsigned long long wlo = w2[2 * q2];
            const unsigned long long whi = w2[2 * q2 + 1];
#pragma unroll
            for (int t = 0; t < TNODES; t++) {
                const ulonglong2 a =
                    *(const ulonglong2*)&agg[cur][t][half * 64 + q2 * 4];
                fma2(acc[t], wlo, a.x);
                fma2(acc[t], whi, a.y);
            }
        }

        // ---- issue next tile's gather into the other buffer ----
        const int ntile = tile + gridDim.x;
        if (ntile < ntiles) {
            const int node = ntile * TNODES + warp;
            unsigned long long a0 = 0ull, a1 = 0ull;
            if (node < nN) {
                const int s = g_row_ptr[node];
                const int e = g_row_ptr[node + 1];
#pragma unroll 4
                for (int j = s; j < e; j++) {
                    const int v = g_v[j];
                    const ulonglong2 xv =
                        *(const ulonglong2*)&xr[(size_t)v * (FDIM / 4) + lane];
                    add2(a0, xv.x);
                    add2(a1, xv.y);
                }
            }
            *(ulonglong2*)&agg[cur ^ 1][warp][lane * 4] =
                make_ulonglong2(a0, a1);
        }

        // ---- cross-half reduction + store ----
        if (half == 1) {
#pragma unroll
            for (int t = 0; t < TNODES; t++) {
                const float2 p = unpackf2(acc[t]);
                red[t][f] = p.x + p.y;
            }
        }
        __syncthreads();
        if (half == 0) {
#pragma unroll
            for (int t = 0; t < TNODES; t++) {
                const int node = tile * TNODES + t;
                if (node < nN) {
                    const float2 p = unpackf2(acc[t]);
                    out[(size_t)node * FDIM + f] = p.x + p.y + red[t][f] + b;
                }
            }
        }
    }
}

// ---------------------------------------------------------------------------
extern "C" void kernel_launch(void* const* d_in, const int* in_sizes, int n_in,
                              void* d_out, int out_size) {
    const float* x = (const float*)d_in[0];
    const void* edges = d_in[1];
    const float* W = (const float*)d_in[2];
    const float* bias = (const float*)d_in[3];
    float* out = (float*)d_out;

    const int nN = in_sizes[0] / FDIM;
    int E = in_sizes[1] / 2;
    if (E > MAXE) E = MAXE;

    void* g_or_ptr = nullptr;
    cudaGetSymbolAddress(&g_or_ptr, g_or);
    cudaMemsetAsync(g_or_ptr, 0, sizeof(unsigned int));

    detect_k<<<148, 256>>>((const unsigned int*)edges, E);
    convert_k<<<296, 256>>>(edges, E);
    rowptr_k<<<(nN + 1 + 255) / 256, 256>>>(edges, E, nN);
    fused_k<<<GRIDSZ, THREADS>>>(x, W, bias, out, nN);
}

// round 4
// speedup vs baseline: 1.2552x; 1.2552x over previous
#include <cuda_runtime.h>
#include <cuda_bf16.h>
#include <cstdint>

#define FDIM 128
#define MAXN 50001
#define NPAD 50176      // 392 * 128, padded node count
#define MAXE 1000000
#define WPITCH 136      // smem/global pitch in halfwords (17x16B, conflict-free frags)

// ---------------------------------------------------------------------------
// Device scratch (allocation-free per harness rules)
__device__ unsigned int g_ctrl[2];               // [0]=dtype flag (0 => int64), [1]=ticket
__device__ int g_row_ptr[MAXN];
__device__ int g_v[MAXE];
__device__ __nv_bfloat16 g_ahi[(size_t)NPAD * FDIM];
__device__ __nv_bfloat16 g_alo[(size_t)NPAD * FDIM];
__device__ __nv_bfloat16 g_wthi[FDIM * WPITCH]; // W^T hi  [n][k], padded pitch
__device__ __nv_bfloat16 g_wtlo[FDIM * WPITCH]; // W^T lo

// ---------------------------------------------------------------------------
// 1) dtype detect: for int64 edges the odd 32-bit words of the u row are 0.
__global__ void detect_k(const unsigned int* __restrict__ w, int E) {
    unsigned int local = 0;
    for (int i = blockIdx.x * blockDim.x + threadIdx.x; i < E;
         i += gridDim.x * blockDim.x)
        local |= w[2 * i + 1];
    if (local) atomicOr(&g_ctrl[0], 1u);
}

// 2) prep: convert v->int32, CSR row_ptr (u sorted), W^T hi/lo bf16 split.
__global__ void prep_k(const void* __restrict__ edges,
                       const float* __restrict__ W, int E, int nN) {
    const bool is64 = (g_ctrl[0] == 0);
    const long long* e64 = (const long long*)edges;
    const int* e32 = (const int*)edges;
    for (int i = blockIdx.x * blockDim.x + threadIdx.x; i < E;
         i += gridDim.x * blockDim.x) {
        g_v[i] = is64 ? (int)e64[E + i] : e32[E + i];
        if (i <= nN) {
            if (i == nN) g_row_ptr[nN] = E;
            else {
                int lo = 0, hi = E;
                while (lo < hi) {
                    int mid = (lo + hi) >> 1;
                    long long um = is64 ? e64[mid] : (long long)e32[mid];
                    if (um < (long long)i) lo = mid + 1; else hi = mid;
                }
                g_row_ptr[i] = lo;
            }
        }
        if (i < FDIM * FDIM) {
            const int n = i >> 7, k = i & 127;
            const float w = W[k * FDIM + n];
            const __nv_bfloat16 h = __float2bfloat16(w);
            g_wthi[n * WPITCH + k] = h;
            g_wtlo[n * WPITCH + k] = __float2bfloat16(w - __bfloat162float(h));
        }
    }
}

// 3) aggregate: ticket-scheduled warp-per-node gather, bf16 hi/lo output.
__global__ void __launch_bounds__(256) agg_k(const float* __restrict__ x, int nN) {
    const int lane = threadIdx.x & 31;
    const float4* __restrict__ xr = (const float4*)x;
    while (true) {
        unsigned int node;
        if (lane == 0) node = atomicAdd(&g_ctrl[1], 1u);
        node = __shfl_sync(0xffffffffu, node, 0);
        if (node >= NPAD) return;
        float4 acc = make_float4(0.f, 0.f, 0.f, 0.f);
        if ((int)node < nN) {
            const int s = g_row_ptr[node];
            const int e = g_row_ptr[node + 1];
            for (int base = s; base < e; base += 32) {
                const int rem = e - base;
                const int myv = (lane < rem) ? g_v[base + lane] : 0;
                const int cnt = rem < 32 ? rem : 32;
#pragma unroll 4
                for (int j = 0; j < cnt; j++) {
                    const int v = __shfl_sync(0xffffffffu, myv, j);
                    const float4 xv = __ldg(&xr[(size_t)v * (FDIM / 4) + lane]);
                    acc.x += xv.x; acc.y += xv.y; acc.z += xv.z; acc.w += xv.w;
                }
            }
        }
        ushort4 hi, lo;
        {
            __nv_bfloat16 h, l;
            h = __float2bfloat16(acc.x); l = __float2bfloat16(acc.x - __bfloat162float(h));
            hi.x = *(unsigned short*)&h; lo.x = *(unsigned short*)&l;
            h = __float2bfloat16(acc.y); l = __float2bfloat16(acc.y - __bfloat162float(h));
            hi.y = *(unsigned short*)&h; lo.y = *(unsigned short*)&l;
            h = __float2bfloat16(acc.z); l = __float2bfloat16(acc.z - __bfloat162float(h));
            hi.z = *(unsigned short*)&h; lo.z = *(unsigned short*)&l;
            h = __float2bfloat16(acc.w); l = __float2bfloat16(acc.w - __bfloat162float(h));
            hi.w = *(unsigned short*)&h; lo.w = *(unsigned short*)&l;
        }
        const size_t o = (size_t)node * FDIM + lane * 4;
        *(ushort4*)&g_ahi[o] = hi;
        *(ushort4*)&g_alo[o] = lo;
    }
}

// ---------------------------------------------------------------------------
// 4) GEMM: out = agg @ W + bias via mma.sync.m16n8k16 bf16, 3-pass hi/lo split.
//    Block: 256 threads (8 warps), M-tile 128 (16 rows/warp), N=K=128.
//    SMEM tiles pitch 136 halfwords -> frag LDS bank = 4*(t/4)+(t%4): bijective,
//    conflict-free without swizzle.
__device__ __forceinline__ void mma_bf16(float* c, const uint32_t* a, const uint32_t* b) {
    asm volatile(
        "mma.sync.aligned.m16n8k16.row.col.f32.bf16.bf16.f32 "
        "{%0,%1,%2,%3}, {%4,%5,%6,%7}, {%8,%9}, {%0,%1,%2,%3};"
        : "+f"(c[0]), "+f"(c[1]), "+f"(c[2]), "+f"(c[3])
        : "r"(a[0]), "r"(a[1]), "r"(a[2]), "r"(a[3]), "r"(b[0]), "r"(b[1]));
}

#define SM_AHI 0
#define SM_ALO (128 * WPITCH)
#define SM_BHI (2 * 128 * WPITCH)
#define SM_BLO (3 * 128 * WPITCH)
#define SM_HALFWORDS (4 * 128 * WPITCH)
#define SM_BYTES (SM_HALFWORDS * 2)

__global__ void __launch_bounds__(256) gemm_k(const float* __restrict__ bias,
                                              float* __restrict__ out, int nN) {
    extern __shared__ __align__(16) unsigned short smem[];
    const int tid = threadIdx.x;
    const int wid = tid >> 5, lane = tid & 31;
    const int mbase = blockIdx.x * 128;

    // Stage A tiles (re-pitch 128 -> 136) and B tiles (straight copy).
    {
        const uint4* __restrict__ sh = (const uint4*)(g_ahi + (size_t)mbase * FDIM);
        const uint4* __restrict__ sl = (const uint4*)(g_alo + (size_t)mbase * FDIM);
#pragma unroll
        for (int i = 0; i < 8; i++) {
            const int idx = i * 256 + tid;       // 0..2047 : row*16 + chunk
            const int row = idx >> 4, c = idx & 15;
            const int dst = (row * WPITCH + c * 8) >> 3;  // uint4 index
            ((uint4*)(smem + SM_AHI))[dst] = sh[idx];
            ((uint4*)(smem + SM_ALO))[dst] = sl[idx];
        }
        const uint4* __restrict__ bh = (const uint4*)g_wthi;
        const uint4* __restrict__ bl = (const uint4*)g_wtlo;
#pragma unroll
        for (int i = 0; i < 9; i++) {
            const int idx = i * 256 + tid;       // 0..2175 covers 128*136/8
            if (idx < (128 * WPITCH) / 8) {
                ((uint4*)(smem + SM_BHI))[idx] = bh[idx];
                ((uint4*)(smem + SM_BLO))[idx] = bl[idx];
            }
        }
    }
    __syncthreads();

    const int qr = lane >> 2;          // t/4  : fragment row group
    const int qc = (lane & 3) * 2;     // (t%4)*2 : fragment k/n offset

    float acc[16][4];
#pragma unroll
    for (int nt = 0; nt < 16; nt++)
#pragma unroll
        for (int j = 0; j < 4; j++) acc[nt][j] = 0.f;

    const int arow = wid * 16 + qr;    // A row within tile for a0/a2
#pragma unroll
    for (int ks = 0; ks < 8; ks++) {
        const int k0 = ks * 16 + qc;
        uint32_t ahi[4], alo[4];
        ahi[0] = *(const uint32_t*)&smem[SM_AHI + arow * WPITCH + k0];
        ahi[1] = *(const uint32_t*)&smem[SM_AHI + (arow + 8) * WPITCH + k0];
        ahi[2] = *(const uint32_t*)&smem[SM_AHI + arow * WPITCH + k0 + 8];
        ahi[3] = *(const uint32_t*)&smem[SM_AHI + (arow + 8) * WPITCH + k0 + 8];
        alo[0] = *(const uint32_t*)&smem[SM_ALO + arow * WPITCH + k0];
        alo[1] = *(const uint32_t*)&smem[SM_ALO + (arow + 8) * WPITCH + k0];
        alo[2] = *(const uint32_t*)&smem[SM_ALO + arow * WPITCH + k0 + 8];
        alo[3] = *(const uint32_t*)&smem[SM_ALO + (arow + 8) * WPITCH + k0 + 8];
#pragma unroll
        for (int nt = 0; nt < 16; nt++) {
            const int brow = nt * 8 + qr;
            uint32_t bhi[2], blo[2];
            bhi[0] = *(const uint32_t*)&smem[SM_BHI + brow * WPITCH + k0];
            bhi[1] = *(const uint32_t*)&smem[SM_BHI + brow * WPITCH + k0 + 8];
            blo[0] = *(const uint32_t*)&smem[SM_BLO + brow * WPITCH + k0];
            blo[1] = *(const uint32_t*)&smem[SM_BLO + brow * WPITCH + k0 + 8];
            mma_bf16(acc[nt], ahi, bhi);
            mma_bf16(acc[nt], ahi, blo);
            mma_bf16(acc[nt], alo, bhi);
        }
    }

    // Epilogue: c0,c1 -> row m0+qr ; c2,c3 -> row m0+qr+8 ; cols nt*8+qc..+1
    const int m0 = mbase + wid * 16 + qr;
#pragma unroll
    for (int nt = 0; nt < 16; nt++) {
        const int n0 = nt * 8 + qc;
        const float2 bv = *(const float2*)&bias[n0];
        if (m0 < nN) {
            float2 r = make_float2(acc[nt][0] + bv.x, acc[nt][1] + bv.y);
            *(float2*)&out[(size_t)m0 * FDIM + n0] = r;
        }
        if (m0 + 8 < nN) {
            float2 r = make_float2(acc[nt][2] + bv.x, acc[nt][3] + bv.y);
            *(float2*)&out[(size_t)(m0 + 8) * FDIM + n0] = r;
        }
    }
}

// ---------------------------------------------------------------------------
extern "C" void kernel_launch(void* const* d_in, const int* in_sizes, int n_in,
                              void* d_out, int out_size) {
    const float* x = (const float*)d_in[0];
    const void* edges = d_in[1];
    const float* W = (const float*)d_in[2];
    const float* bias = (const float*)d_in[3];
    float* out = (float*)d_out;

    const int nN = in_sizes[0] / FDIM;
    int E = in_sizes[1] / 2;
    if (E > MAXE) E = MAXE;

    void* ctrl = nullptr;
    cudaGetSymbolAddress(&ctrl, g_ctrl);
    cudaMemsetAsync(ctrl, 0, 2 * sizeof(unsigned int));

    cudaFuncSetAttribute(gemm_k, cudaFuncAttributeMaxDynamicSharedMemorySize, SM_BYTES);

    detect_k<<<148, 256>>>((const unsigned int*)edges, E);
    prep_k<<<296, 256>>>(edges, W, E, nN);
    agg_k<<<1184, 256>>>(x, nN);
    gemm_k<<<NPAD / 128, 256, SM_BYTES>>>(bias, out, nN);
}

// round 5
// speedup vs baseline: 1.8312x; 1.4589x over previous
#include <cuda_runtime.h>
#include <cuda_bf16.h>
#include <cstdint>

#define FDIM 128
#define MAXN 50001
#define NPAD 50176      // 392 * 128, padded node count
#define MAXE 1000000
#define WPITCH 136      // B pitch in halfwords (17x16B, conflict-free frags)

// ---------------------------------------------------------------------------
// Device scratch (allocation-free per harness rules)
__device__ unsigned int g_ctrl[1];               // [0]=dtype flag (0 => int64)
__device__ int g_row_ptr[MAXN];
__device__ int g_v[MAXE];
// Aggregate, interleaved hi/lo pairs: row r, even k -> halves at
// r*256 + 2k + {0,1,2,3} = {hi(k), hi(k+1), lo(k), lo(k+1)}
__device__ __nv_bfloat16 g_a[(size_t)NPAD * 256];
__device__ __nv_bfloat16 g_wthi[FDIM * WPITCH]; // W^T hi  [n][k], padded pitch
__device__ __nv_bfloat16 g_wtlo[FDIM * WPITCH]; // W^T lo

// ---------------------------------------------------------------------------
// 1) dtype detect: for int64 edges the odd 32-bit words of the u row are 0.
__global__ void detect_k(const unsigned int* __restrict__ w, int E) {
    unsigned int local = 0;
    for (int i = blockIdx.x * blockDim.x + threadIdx.x; i < E;
         i += gridDim.x * blockDim.x)
        local |= w[2 * i + 1];
    if (local) atomicOr(&g_ctrl[0], 1u);
}

// 2) prep: convert v->int32, CSR row_ptr (u sorted), W^T hi/lo bf16 split.
__global__ void prep_k(const void* __restrict__ edges,
                       const float* __restrict__ W, int E, int nN) {
    const bool is64 = (g_ctrl[0] == 0);
    const long long* e64 = (const long long*)edges;
    const int* e32 = (const int*)edges;
    for (int i = blockIdx.x * blockDim.x + threadIdx.x; i < E;
         i += gridDim.x * blockDim.x) {
        g_v[i] = is64 ? (int)e64[E + i] : e32[E + i];
        if (i <= nN) {
            if (i == nN) g_row_ptr[nN] = E;
            else {
                int lo = 0, hi = E;
                while (lo < hi) {
                    int mid = (lo + hi) >> 1;
                    long long um = is64 ? e64[mid] : (long long)e32[mid];
                    if (um < (long long)i) lo = mid + 1; else hi = mid;
                }
                g_row_ptr[i] = lo;
            }
        }
        if (i < FDIM * FDIM) {
            const int n = i >> 7, k = i & 127;
            const float w = W[k * FDIM + n];
            const __nv_bfloat16 h = __float2bfloat16(w);
            g_wthi[n * WPITCH + k] = h;
            g_wtlo[n * WPITCH + k] = __float2bfloat16(w - __bfloat162float(h));
        }
    }
}

// ---------------------------------------------------------------------------
// 3) aggregate: static warp-per-node (no atomics, no shuffles), fp32 accum,
//    interleaved bf16 hi/lo pair output.
__device__ __forceinline__ uint32_t pack_hi2(float a, float b) {
    uint32_t r;
    asm("cvt.rn.bf16x2.f32 %0, %1, %2;" : "=r"(r) : "f"(b), "f"(a));
    return r;
}
__device__ __forceinline__ float bf16_of(float a) {
    __nv_bfloat16 h = __float2bfloat16(a);
    return __bfloat162float(h);
}

__global__ void __launch_bounds__(256) agg_k(const float* __restrict__ x, int nN) {
    const int lane = threadIdx.x & 31;
    const int gw = (blockIdx.x * blockDim.x + threadIdx.x) >> 5;
    const int nw = (gridDim.x * blockDim.x) >> 5;
    const float4* __restrict__ xr = (const float4*)x;
    uint4* __restrict__ ga4 = (uint4*)g_a;

    for (int node = gw; node < NPAD; node += nw) {
        float4 accA = make_float4(0.f, 0.f, 0.f, 0.f);
        float4 accB = make_float4(0.f, 0.f, 0.f, 0.f);
        if (node < nN) {
            const int s = g_row_ptr[node];
            const int e = g_row_ptr[node + 1];
            int j = s;
            for (; j + 4 <= e; j += 4) {
                const int v0 = g_v[j + 0];
                const int v1 = g_v[j + 1];
                const int v2 = g_v[j + 2];
                const int v3 = g_v[j + 3];
                const float4 x0 = __ldg(&xr[(size_t)v0 * 32 + lane]);
                const float4 x1 = __ldg(&xr[(size_t)v1 * 32 + lane]);
                const float4 x2 = __ldg(&xr[(size_t)v2 * 32 + lane]);
                const float4 x3 = __ldg(&xr[(size_t)v3 * 32 + lane]);
                accA.x += x0.x; accA.y += x0.y; accA.z += x0.z; accA.w += x0.w;
                accB.x += x1.x; accB.y += x1.y; accB.z += x1.z; accB.w += x1.w;
                accA.x += x2.x; accA.y += x2.y; accA.z += x2.z; accA.w += x2.w;
                accB.x += x3.x; accB.y += x3.y; accB.z += x3.z; accB.w += x3.w;
            }
            for (; j < e; j++) {
                const int v = g_v[j];
                const float4 xv = __ldg(&xr[(size_t)v * 32 + lane]);
                accA.x += xv.x; accA.y += xv.y; accA.z += xv.z; accA.w += xv.w;
            }
            accA.x += accB.x; accA.y += accB.y; accA.z += accB.z; accA.w += accB.w;
        }
        // hi/lo split, interleaved pairs: {hi(k),hi(k+1),lo(k),lo(k+1)} per 8B
        uint4 o;
        o.x = pack_hi2(accA.x, accA.y);
        o.y = pack_hi2(accA.x - bf16_of(accA.x), accA.y - bf16_of(accA.y));
        o.z = pack_hi2(accA.z, accA.w);
        o.w = pack_hi2(accA.z - bf16_of(accA.z), accA.w - bf16_of(accA.w));
        ga4[(size_t)node * 32 + lane] = o;
    }
}

// ---------------------------------------------------------------------------
// 4) GEMM: out = agg @ W + bias via mma.sync.m16n8k16 bf16, 3-pass hi/lo split.
//    smem holds ONLY B (hi/lo, 69.6KB) -> 2 blocks/SM. A fragments come
//    straight from L2 via one LDG.64 per (rowpair, kpair) in the interleaved
//    layout. Warp w owns rows [w*16, w*16+16) of the 128-row M tile, all N.
__device__ __forceinline__ void mma_bf16(float* c, const uint32_t* a, const uint32_t* b) {
    asm volatile(
        "mma.sync.aligned.m16n8k16.row.col.f32.bf16.bf16.f32 "
        "{%0,%1,%2,%3}, {%4,%5,%6,%7}, {%8,%9}, {%0,%1,%2,%3};"
        : "+f"(c[0]), "+f"(c[1]), "+f"(c[2]), "+f"(c[3])
        : "r"(a[0]), "r"(a[1]), "r"(a[2]), "r"(a[3]), "r"(b[0]), "r"(b[1]));
}

#define SM_BHI 0
#define SM_BLO (128 * WPITCH)
#define SM_BYTES (2 * 128 * WPITCH * 2)

__global__ void __launch_bounds__(256, 2) gemm_k(const float* __restrict__ bias,
                                                 float* __restrict__ out, int nN) {
    extern __shared__ __align__(16) unsigned short smem[];
    const int tid = threadIdx.x;
    const int wid = tid >> 5, lane = tid & 31;
    const int mbase = blockIdx.x * 128;

    // Stage B tiles (straight copy, already WPITCH-pitched in global).
    {
        const uint4* __restrict__ bh = (const uint4*)g_wthi;
        const uint4* __restrict__ bl = (const uint4*)g_wtlo;
#pragma unroll
        for (int i = 0; i < 9; i++) {
            const int idx = i * 256 + tid;
            if (idx < (128 * WPITCH) / 8) {
                ((uint4*)(smem + SM_BHI))[idx] = bh[idx];
                ((uint4*)(smem + SM_BLO))[idx] = bl[idx];
            }
        }
    }
    __syncthreads();

    const int qr = lane >> 2;          // fragment row within 8-row group
    const int qc = (lane & 3) * 2;     // fragment k/n offset

    float acc[16][4];
#pragma unroll
    for (int nt = 0; nt < 16; nt++)
#pragma unroll
        for (int j = 0; j < 4; j++) acc[nt][j] = 0.f;

    const uint2* __restrict__ ga = (const uint2*)g_a;   // 8B = {hi2, lo2} pair
    const int row0 = mbase + wid * 16 + qr;
    const int row1 = row0 + 8;

    // A fragment fetch for k-step ks: (row0|row1) x (k0|k0+8), one LDG.64 each.
    uint2 nx0, nx1, nx2, nx3;
    {
        const int kk = qc;             // ks = 0
        nx0 = __ldg(&ga[(size_t)row0 * 64 + (kk >> 1)]);
        nx1 = __ldg(&ga[(size_t)row1 * 64 + (kk >> 1)]);
        nx2 = __ldg(&ga[(size_t)row0 * 64 + ((kk + 8) >> 1)]);
        nx3 = __ldg(&ga[(size_t)row1 * 64 + ((kk + 8) >> 1)]);
    }

#pragma unroll
    for (int ks = 0; ks < 8; ks++) {
        uint32_t ahi[4] = {nx0.x, nx1.x, nx2.x, nx3.x};
        uint32_t alo[4] = {nx0.y, nx1.y, nx2.y, nx3.y};
        if (ks < 7) {                  // prefetch next k-step
            const int kk = (ks + 1) * 16 + qc;
            nx0 = __ldg(&ga[(size_t)row0 * 64 + (kk >> 1)]);
            nx1 = __ldg(&ga[(size_t)row1 * 64 + (kk >> 1)]);
            nx2 = __ldg(&ga[(size_t)row0 * 64 + ((kk + 8) >> 1)]);
            nx3 = __ldg(&ga[(size_t)row1 * 64 + ((kk + 8) >> 1)]);
        }
        const int k0 = ks * 16 + qc;
#pragma unroll
        for (int nt = 0; nt < 16; nt++) {
            const int brow = nt * 8 + qr;
            uint32_t bhi[2], blo[2];
            bhi[0] = *(const uint32_t*)&smem[SM_BHI + brow * WPITCH + k0];
            bhi[1] = *(const uint32_t*)&smem[SM_BHI + brow * WPITCH + k0 + 8];
            blo[0] = *(const uint32_t*)&smem[SM_BLO + brow * WPITCH + k0];
            blo[1] = *(const uint32_t*)&smem[SM_BLO + brow * WPITCH + k0 + 8];
            mma_bf16(acc[nt], ahi, bhi);
            mma_bf16(acc[nt], ahi, blo);
            mma_bf16(acc[nt], alo, bhi);
        }
    }

    // Epilogue: c0,c1 -> row m0 ; c2,c3 -> row m0+8 ; cols nt*8+qc..+1
    const int m0 = mbase + wid * 16 + qr;
#pragma unroll
    for (int nt = 0; nt < 16; nt++) {
        const int n0 = nt * 8 + qc;
        const float2 bv = *(const float2*)&bias[n0];
        if (m0 < nN) {
            float2 r = make_float2(acc[nt][0] + bv.x, acc[nt][1] + bv.y);
            *(float2*)&out[(size_t)m0 * FDIM + n0] = r;
        }
        if (m0 + 8 < nN) {
            float2 r = make_float2(acc[nt][2] + bv.x, acc[nt][3] + bv.y);
            *(float2*)&out[(size_t)(m0 + 8) * FDIM + n0] = r;
        }
    }
}

// ---------------------------------------------------------------------------
extern "C" void kernel_launch(void* const* d_in, const int* in_sizes, int n_in,
                              void* d_out, int out_size) {
    const float* x = (const float*)d_in[0];
    const void* edges = d_in[1];
    const float* W = (const float*)d_in[2];
    const float* bias = (const float*)d_in[3];
    float* out = (float*)d_out;

    const int nN = in_sizes[0] / FDIM;
    int E = in_sizes[1] / 2;
    if (E > MAXE) E = MAXE;

    void* ctrl = nullptr;
    cudaGetSymbolAddress(&ctrl, g_ctrl);
    cudaMemsetAsync(ctrl, 0, sizeof(unsigned int));

    cudaFuncSetAttribute(gemm_k, cudaFuncAttributeMaxDynamicSharedMemorySize, SM_BYTES);

    detect_k<<<148, 256>>>((const unsigned int*)edges, E);
    prep_k<<<296, 256>>>(edges, W, E, nN);
    agg_k<<<1184, 256>>>(x, nN);
    gemm_k<<<NPAD / 128, 256, SM_BYTES>>>(bias, out, nN);
}